// round 11
// baseline (speedup 1.0000x reference)
#include <cuda_runtime.h>
#include <cuda_bf16.h>
#include <cstdint>

// Problem constants: (b=4, n=8, d=64, s=8192) fp32
#define DD 64
#define SS 8192
#define NHEADS 32

// kB config
#define NCB 32
#define CHUNKB (SS / NCB)     // 256
#define NKSTEP (CHUNKB / 16)  // 16

// kC config
#define SCT 64                // s-tile per block
#define KC_SMEM (16384 + 16384 + 256)

// Scratch
__device__ float g_Upart[NHEADS * NCB * DD * DD];
__device__ float g_Zpart[NHEADS * NCB * DD];
__device__ unsigned short g_Cthi[NHEADS * DD * DD];  // C^T hi, [h][j][i] bf16 bits
__device__ unsigned short g_Ctlo[NHEADS * DD * DD];  // C^T lo

// ============================ helpers ============================
__device__ __forceinline__ uint32_t smem_u32(const void* p) {
    uint32_t a;
    asm("{ .reg .u64 t; cvta.to.shared.u64 t, %1; cvt.u32.u64 %0, t; }" : "=r"(a) : "l"(p));
    return a;
}
__device__ __forceinline__ uint32_t swz(uint32_t row, uint32_t sbyte, uint32_t pitch) {
    return row * pitch + (sbyte ^ ((row & 7u) << 4));
}
__device__ __forceinline__ void ldsm_x4(uint32_t& r0, uint32_t& r1, uint32_t& r2, uint32_t& r3, uint32_t a) {
    asm volatile("ldmatrix.sync.aligned.m8n8.x4.shared.b16 {%0,%1,%2,%3}, [%4];"
                 : "=r"(r0), "=r"(r1), "=r"(r2), "=r"(r3) : "r"(a));
}
__device__ __forceinline__ void ldsm_x2t(uint32_t& r0, uint32_t& r1, uint32_t a) {
    asm volatile("ldmatrix.sync.aligned.m8n8.x2.trans.shared.b16 {%0,%1}, [%2];"
                 : "=r"(r0), "=r"(r1) : "r"(a));
}
__device__ __forceinline__ void mma_bf16(float* d, const uint32_t* a, uint32_t b0, uint32_t b1) {
    asm volatile("mma.sync.aligned.m16n8k16.row.col.f32.bf16.bf16.f32 "
                 "{%0,%1,%2,%3}, {%4,%5,%6,%7}, {%8,%9}, {%0,%1,%2,%3};"
                 : "+f"(d[0]), "+f"(d[1]), "+f"(d[2]), "+f"(d[3])
                 : "r"(a[0]), "r"(a[1]), "r"(a[2]), "r"(a[3]), "r"(b0), "r"(b1));
}
__device__ __forceinline__ uint32_t cvt2(float hi, float lo) {  // d = {low:lo, high:hi}
    uint32_t r;
    asm("cvt.rn.bf16x2.f32 %0, %1, %2;" : "=r"(r) : "f"(hi), "f"(lo));
    return r;
}
// Split fp32 pair (x = elem k, y = elem k+1) into packed hi / lo bf16x2 frags.
__device__ __forceinline__ void split2(float x, float y, uint32_t& hi, uint32_t& lo) {
    const uint32_t ux = __float_as_uint(x), uy = __float_as_uint(y);
    hi = __byte_perm(ux, uy, 0x7632);  // {low: x_hi, high: y_hi}
    const float lx = x - __uint_as_float(ux & 0xFFFF0000u);
    const float ly = y - __uint_as_float(uy & 0xFFFF0000u);
    lo = cvt2(ly, lx);
}
// smem store variant (kC): split 4 fp32 into hi row and lo row (row+64).
__device__ __forceinline__ void store_split(char* base, int row, int sbyte, uint32_t pitch,
                                            float a0, float a1, float a2, float a3) {
    uint32_t h01, l01, h23, l23;
    split2(a0, a1, h01, l01);
    split2(a2, a3, h23, l23);
    *(uint2*)(base + swz(row, sbyte, pitch))      = make_uint2(h01, h23);
    *(uint2*)(base + swz(row + 64, sbyte, pitch)) = make_uint2(l01, l23);
}

// ============================================================================
// kB: per (h, c): U_part[64i][64j] = sum_s exp(k[i,s]) v[j,s]; Z_part[i].
// Smem-free: fragments loaded directly from global (8B/lane coalesced),
// exp + bf16 2-split in registers, no barriers in the main loop.
// 256 thr / 8 warps; warp tile 16(i) x 32(j).
// ============================================================================
__global__ __launch_bounds__(256, 3) void kB(const float* __restrict__ K,
                                             const float* __restrict__ V) {
    const int tid = threadIdx.x;
    const int w = tid >> 5, lane = tid & 31;
    const int h = blockIdx.y, c = blockIdx.x;
    const float* kh = K + (size_t)h * DD * SS + c * CHUNKB;
    const float* vh = V + (size_t)h * DD * SS + c * CHUNKB;

    const int mt = w & 3;    // i-tile (16 rows)
    const int nh = w >> 2;   // j-half (32 cols)
    const int r = lane >> 2;         // fragment row/col within 8
    const int kp = 2 * (lane & 3);   // k-pair base within k16
    const int i0 = 16 * mt;

    // A row pointers (rows i0+r and i0+8+r), advance by 16 per k-step.
    const float* pA0 = kh + (size_t)(i0 + r) * SS + kp;
    const float* pA1 = pA0 + 8 * SS;
    // B col pointers: 4 n-tiles, col 32*nh + 8*t + r.
    const float* pB[4];
    #pragma unroll
    for (int t = 0; t < 4; ++t)
        pB[t] = vh + (size_t)(32 * nh + 8 * t + r) * SS + kp;

    float acc[4][4];
    #pragma unroll
    for (int t = 0; t < 4; t++)
        #pragma unroll
        for (int e = 0; e < 4; e++) acc[t][e] = 0.f;
    float z0 = 0.f, z1 = 0.f;

    #pragma unroll 2
    for (int kk = 0; kk < NKSTEP; ++kk) {
        const int s0 = kk * 16;
        // ---- A fragment: rows i0+r / i0+8+r, k pairs kp and kp+8 ----
        const float2 aw = *(const float2*)(pA0 + s0);       // (row r,   k kp)
        const float2 ax = *(const float2*)(pA0 + s0 + 8);   // (row r,   k kp+8)
        const float2 ay = *(const float2*)(pA1 + s0);       // (row r+8, k kp)
        const float2 az = *(const float2*)(pA1 + s0 + 8);   // (row r+8, k kp+8)
        const float e0 = __expf(aw.x), e1 = __expf(aw.y);
        const float e2 = __expf(ax.x), e3 = __expf(ax.y);
        const float e4 = __expf(ay.x), e5 = __expf(ay.y);
        const float e6 = __expf(az.x), e7 = __expf(az.y);
        z0 += (e0 + e1) + (e2 + e3);
        z1 += (e4 + e5) + (e6 + e7);
        uint32_t ah[4], al[4];
        split2(e0, e1, ah[0], al[0]);   // a0: (row r,   kp)
        split2(e4, e5, ah[1], al[1]);   // a1: (row r+8, kp)
        split2(e2, e3, ah[2], al[2]);   // a2: (row r,   kp+8)
        split2(e6, e7, ah[3], al[3]);   // a3: (row r+8, kp+8)

        // ---- B fragments per n-tile + MMAs ----
        #pragma unroll
        for (int t = 0; t < 4; ++t) {
            const float2 b0 = *(const float2*)(pB[t] + s0);      // (k kp,   col r)
            const float2 b1 = *(const float2*)(pB[t] + s0 + 8);  // (k kp+8, col r)
            uint32_t bh0, bl0, bh1, bl1;
            split2(b0.x, b0.y, bh0, bl0);
            split2(b1.x, b1.y, bh1, bl1);
            mma_bf16(acc[t], ah, bh0, bh1);   // hi*hi
            mma_bf16(acc[t], ah, bl0, bl1);   // hi*lo
            mma_bf16(acc[t], al, bh0, bh1);   // lo*hi
        }
    }

    // Z partials (K rows are duplicated across nh=0/1 warps; only nh==0 writes).
    z0 += __shfl_xor_sync(0xffffffffu, z0, 1);
    z0 += __shfl_xor_sync(0xffffffffu, z0, 2);
    z1 += __shfl_xor_sync(0xffffffffu, z1, 1);
    z1 += __shfl_xor_sync(0xffffffffu, z1, 2);
    if (nh == 0 && (lane & 3) == 0) {
        float* zp = g_Zpart + (h * NCB + c) * DD;
        zp[i0 + r] = z0;
        zp[i0 + 8 + r] = z1;
    }

    // acc -> g_Upart
    float* up = g_Upart + (size_t)(h * NCB + c) * DD * DD;
    const int oi = i0 + (lane >> 2);
    const int oj = 32 * nh + 2 * (lane & 3);
    #pragma unroll
    for (int t = 0; t < 4; ++t) {
        *(float2*)(up + oi * DD + oj + 8 * t)       = make_float2(acc[t][0], acc[t][1]);
        *(float2*)(up + (oi + 8) * DD + oj + 8 * t) = make_float2(acc[t][2], acc[t][3]);
    }
}

// ============================================================================
// kB2: reduce partials -> C^T split bf16: g_Cthi/lo[h][j][i]
// ============================================================================
__global__ void kB2() {
    const int idx = blockIdx.x * 256 + threadIdx.x;
    if (idx >= NHEADS * DD * DD) return;
    const int h = idx >> 12;
    const int ij = idx & 4095;
    const int i = ij >> 6, j = ij & 63;
    float u = 0.f;
    #pragma unroll
    for (int c = 0; c < NCB; c++) u += g_Upart[((size_t)(h * NCB + c) << 12) + ij];
    float z = 0.f;
    #pragma unroll
    for (int c = 0; c < NCB; c++) z += g_Zpart[(h * NCB + c) * DD + i];
    const float cval = u * (0.125f / z);
    const uint32_t ub = __float_as_uint(cval);
    const float hi = __uint_as_float(ub & 0xFFFF0000u);
    const float lo = cval - hi;
    __nv_bfloat16 lb = __float2bfloat16(lo);
    g_Cthi[h * 4096 + j * 64 + i] = (unsigned short)(ub >> 16);
    g_Ctlo[h * 4096 + j * 64 + i] = *(unsigned short*)&lb;
}

// ============================================================================
// kC: per (h, s-tile 64): out[j][s] = rinv[s] * sum_i Ct[j][i] * exp(q[i][s])
// 128 thr / 4 warps; warp owns 16 j-rows x all 64 s. HMMA bf16 2-split.
// ============================================================================
__global__ __launch_bounds__(128) void kC(const float* __restrict__ Q,
                                          float* __restrict__ O) {
    extern __shared__ __align__(1024) char dsm[];
    char* Asm = dsm;               // Ct tile: [128 rows][128B] (j rows hi/lo, 64 i cols)
    char* Bsm = dsm + 16384;       // qe tile: [128 rows][128B] (i rows hi/lo, 64 s cols)
    float* rs = (float*)(dsm + 32768);  // [64]

    const int tid = threadIdx.x;
    const int w = tid >> 5, lane = tid & 31;
    const int h = blockIdx.y;
    const int stile = blockIdx.x;
    const float* qh = Q + (size_t)h * DD * SS + stile * SCT;
    float* oh = O + (size_t)h * DD * SS + stile * SCT;

    // Load C^T hi/lo into swizzled smem (16KB, 8 uint4/thread)
    {
        const unsigned short* src_hi = g_Cthi + h * 4096;
        const unsigned short* src_lo = g_Ctlo + h * 4096;
        #pragma unroll
        for (int e = 0; e < 8; ++e) {
            const int u = tid + 128 * e;
            const int row = u >> 3, sb = (u & 7) * 16;
            const unsigned short* s = (row < 64) ? (src_hi + row * 64 + (u & 7) * 8)
                                                 : (src_lo + (row - 64) * 64 + (u & 7) * 8);
            *(uint4*)(Asm + swz(row, sb, 128)) = *(const uint4*)s;
        }
    }
    // Convert q tile: 64 i x 64 s -> exp -> hi/lo. 8 float4/thread.
    #pragma unroll
    for (int e = 0; e < 8; ++e) {
        const int f = tid + 128 * e;
        const int row = f >> 4, c4 = f & 15;
        const float4 q4 = *(const float4*)(qh + (size_t)row * SS + 4 * c4);
        store_split(Bsm, row, 8 * c4, 128,
                    __expf(q4.x), __expf(q4.y), __expf(q4.z), __expf(q4.w));
    }
    __syncthreads();

    // rinv per s column (threads 0..63 own one s each)
    if (tid < 64) {
        float sum = 0.f;
        #pragma unroll 8
        for (int i = 0; i < 64; ++i) {
            const __nv_bfloat16 bh = *(const __nv_bfloat16*)(Bsm + swz(i, 2 * tid, 128));
            const __nv_bfloat16 bl = *(const __nv_bfloat16*)(Bsm + swz(i + 64, 2 * tid, 128));
            sum += __bfloat162float(bh) + __bfloat162float(bl);
        }
        rs[tid] = 1.0f / sum;
    }
    __syncthreads();

    const uint32_t Au = smem_u32(Asm), Bu = smem_u32(Bsm);

    // A fragments (warp's 16 j-rows, hi & lo), reused across all 8 n-tiles.
    uint32_t ah[4][4], al[4][4];
    {
        const uint32_t rA = 16 * w + (lane & 15);
        #pragma unroll
        for (int kk = 0; kk < 4; ++kk) {
            const uint32_t cb = 32 * kk + 16 * (lane >> 4);
            ldsm_x4(ah[kk][0], ah[kk][1], ah[kk][2], ah[kk][3], Au + swz(rA, cb, 128));
            ldsm_x4(al[kk][0], al[kk][1], al[kk][2], al[kk][3], Au + swz(rA + 64, cb, 128));
        }
    }

    float acc[8][4];
    #pragma unroll
    for (int t = 0; t < 8; t++)
        #pragma unroll
        for (int e = 0; e < 4; e++) acc[t][e] = 0.f;

    const uint32_t rBl = (lane & 7) + 8 * ((lane >> 3) & 1);  // i row within k16
    #pragma unroll
    for (int nt = 0; nt < 8; ++nt) {
        const uint32_t sb = 2 * (8 * nt);  // byte offset of 8-s group
        #pragma unroll
        for (int kk = 0; kk < 4; ++kk) {
            uint32_t bh0, bh1, bl0, bl1;
            ldsm_x2t(bh0, bh1, Bu + swz(16 * kk + rBl, sb, 128));
            ldsm_x2t(bl0, bl1, Bu + swz(16 * kk + rBl + 64, sb, 128));
            mma_bf16(acc[nt], ah[kk], bh0, bh1);   // hi*hi
            mma_bf16(acc[nt], ah[kk], bl0, bl1);   // hi*lo
            mma_bf16(acc[nt], al[kk], bh0, bh1);   // lo*hi
        }
    }

    // Epilogue: scale by rinv and store
    const int j0 = 16 * w + (lane >> 2);
    #pragma unroll
    for (int nt = 0; nt < 8; ++nt) {
        const int sl = 8 * nt + 2 * (lane & 3);
        const float r0 = rs[sl], r1 = rs[sl + 1];
        *(float2*)(oh + (size_t)j0 * SS + sl) =
            make_float2(acc[nt][0] * r0, acc[nt][1] * r1);
        *(float2*)(oh + (size_t)(j0 + 8) * SS + sl) =
            make_float2(acc[nt][2] * r0, acc[nt][3] * r1);
    }
}

extern "C" void kernel_launch(void* const* d_in, const int* in_sizes, int n_in,
                              void* d_out, int out_size) {
    const float* q = (const float*)d_in[0];
    const float* k = (const float*)d_in[1];
    const float* v = (const float*)d_in[2];
    float* out = (float*)d_out;

    cudaFuncSetAttribute(kC, cudaFuncAttributeMaxDynamicSharedMemorySize, KC_SMEM);

    dim3 gB(NCB, NHEADS);
    kB<<<gB, 256>>>(k, v);
    kB2<<<(NHEADS * DD * DD + 255) / 256, 256>>>();
    dim3 gC(SS / SCT, NHEADS);
    kC<<<gC, 128, KC_SMEM>>>(q, out);
}

// round 13
// speedup vs baseline: 1.3490x; 1.3490x over previous
#include <cuda_runtime.h>
#include <cuda_fp16.h>
#include <cstdint>

// Problem constants: (b=4, n=8, d=64, s=8192) fp32
#define DD 64
#define SS 8192
#define NHEADS 32

// kB config
#define NCB 32
#define CHUNKB (SS / NCB)     // 256
#define NSTAGE (CHUNKB / 64)  // 4
#define KB_SMEM 16384         // A(8KB) + B(8KB) fp16

// kC config
#define SCT 64                // s-tile per block
#define KC_SMEM (8192 + 8192 + 256)

// Scratch
__device__ float g_Upart[NHEADS * NCB * DD * DD];
__device__ float g_Zpart[NHEADS * NCB * DD];
__device__ unsigned short g_Cth[NHEADS * DD * DD];  // C^T fp16 bits, [h][j][i]

// ============================ helpers ============================
__device__ __forceinline__ uint32_t smem_u32(const void* p) {
    uint32_t a;
    asm("{ .reg .u64 t; cvta.to.shared.u64 t, %1; cvt.u32.u64 %0, t; }" : "=r"(a) : "l"(p));
    return a;
}
// XOR swizzle: 16B chunk permute within 128B, keyed by row.
__device__ __forceinline__ uint32_t swz(uint32_t row, uint32_t sbyte, uint32_t pitch) {
    return row * pitch + (sbyte ^ ((row & 7u) << 4));
}
__device__ __forceinline__ void ldsm_x4(uint32_t& r0, uint32_t& r1, uint32_t& r2, uint32_t& r3, uint32_t a) {
    asm volatile("ldmatrix.sync.aligned.m8n8.x4.shared.b16 {%0,%1,%2,%3}, [%4];"
                 : "=r"(r0), "=r"(r1), "=r"(r2), "=r"(r3) : "r"(a));
}
__device__ __forceinline__ void ldsm_x2t(uint32_t& r0, uint32_t& r1, uint32_t a) {
    asm volatile("ldmatrix.sync.aligned.m8n8.x2.trans.shared.b16 {%0,%1}, [%2];"
                 : "=r"(r0), "=r"(r1) : "r"(a));
}
__device__ __forceinline__ void mma_f16(float* d, const uint32_t* a, uint32_t b0, uint32_t b1) {
    asm volatile("mma.sync.aligned.m16n8k16.row.col.f32.f16.f16.f32 "
                 "{%0,%1,%2,%3}, {%4,%5,%6,%7}, {%8,%9}, {%0,%1,%2,%3};"
                 : "+f"(d[0]), "+f"(d[1]), "+f"(d[2]), "+f"(d[3])
                 : "r"(a[0]), "r"(a[1]), "r"(a[2]), "r"(a[3]), "r"(b0), "r"(b1));
}
__device__ __forceinline__ uint32_t cvt2h(float hi, float lo) {  // {high:hi, low:lo}
    uint32_t r;
    asm("cvt.rn.f16x2.f32 %0, %1, %2;" : "=r"(r) : "f"(hi), "f"(lo));
    return r;
}
// Store 4 fp32 as fp16x4 (8B) at swizzled [row][col 4*c4].
__device__ __forceinline__ void store_h4(char* base, int row, int c4, uint32_t pitch,
                                         float a0, float a1, float a2, float a3) {
    *(uint2*)(base + swz(row, 8 * c4, pitch)) = make_uint2(cvt2h(a1, a0), cvt2h(a3, a2));
}

// ============================================================================
// kB: per (h, c): U_part[64i][64j] = sum_s exp(k[i,s]) v[j,s]; Z_part[i].
// fp16 HMMA single-pass (fp32 accum). 256 thr / 8 warps; warp tile 16i x 32j.
// ============================================================================
__global__ __launch_bounds__(256) void kB(const float* __restrict__ K,
                                          const float* __restrict__ V) {
    extern __shared__ __align__(1024) char dsm[];
    const int tid = threadIdx.x;
    const int w = tid >> 5, lane = tid & 31;
    const int h = blockIdx.y, c = blockIdx.x;
    const float* kh = K + (size_t)h * DD * SS + c * CHUNKB;
    const float* vh = V + (size_t)h * DD * SS + c * CHUNKB;

    const int mt = w & 3;    // i-tile (16 rows)
    const int nh = w >> 2;   // j-half (32 cols)

    float acc[4][4];
    #pragma unroll
    for (int t = 0; t < 4; t++)
        #pragma unroll
        for (int e = 0; e < 4; e++) acc[t][e] = 0.f;
    float zacc[4] = {0.f, 0.f, 0.f, 0.f};

    char* As = dsm;          // expK fp16 [64][64], pitch 128B
    char* Bs = dsm + 8192;   // V    fp16 [64][64], pitch 128B
    const uint32_t Au = smem_u32(As), Bu = smem_u32(Bs);
    const uint32_t rA = 16 * mt + (lane & 15);
    const uint32_t rB = 32 * nh + (lane & 15);

    for (int stage = 0; stage < NSTAGE; ++stage) {
        const int s0 = stage * 64;
        if (stage > 0) __syncthreads();
        // convert: 64 rows x 64 s of K (exp) and V -> fp16
        #pragma unroll
        for (int e = 0; e < 4; ++e) {
            const int f = tid + 256 * e;
            const int row = f >> 4, c4 = f & 15;
            const float4 k4 = *(const float4*)(kh + (size_t)row * SS + s0 + 4 * c4);
            const float e0 = __expf(k4.x), e1 = __expf(k4.y),
                        e2 = __expf(k4.z), e3 = __expf(k4.w);
            zacc[e] += (e0 + e1) + (e2 + e3);
            store_h4(As, row, c4, 128, e0, e1, e2, e3);
            const float4 v4 = *(const float4*)(vh + (size_t)row * SS + s0 + 4 * c4);
            store_h4(Bs, row, c4, 128, v4.x, v4.y, v4.z, v4.w);
        }
        __syncthreads();
        #pragma unroll
        for (int kk = 0; kk < 4; ++kk) {
            const uint32_t cb = 32 * kk + 16 * (lane >> 4);
            uint32_t a[4];
            ldsm_x4(a[0], a[1], a[2], a[3], Au + swz(rA, cb, 128));
            uint32_t b0[4], b1[4];
            ldsm_x4(b0[0], b0[1], b0[2], b0[3], Bu + swz(rB, cb, 128));
            ldsm_x4(b1[0], b1[1], b1[2], b1[3], Bu + swz(rB + 16, cb, 128));
            mma_f16(acc[0], a, b0[0], b0[2]);
            mma_f16(acc[1], a, b0[1], b0[3]);
            mma_f16(acc[2], a, b1[0], b1[2]);
            mma_f16(acc[3], a, b1[1], b1[3]);
        }
    }

    // Z partials: 16 threads share each loader row-group.
    {
        float* zp = g_Zpart + (h * NCB + c) * DD;
        #pragma unroll
        for (int e = 0; e < 4; ++e) {
            float z = zacc[e];
            z += __shfl_down_sync(0xffffffffu, z, 8, 16);
            z += __shfl_down_sync(0xffffffffu, z, 4, 16);
            z += __shfl_down_sync(0xffffffffu, z, 2, 16);
            z += __shfl_down_sync(0xffffffffu, z, 1, 16);
            if ((tid & 15) == 0) zp[(tid >> 4) + 16 * e] = z;
        }
    }

    // acc -> g_Upart
    float* up = g_Upart + (size_t)(h * NCB + c) * DD * DD;
    const int i0 = 16 * mt + (lane >> 2);
    const int j0 = 32 * nh + 2 * (lane & 3);
    #pragma unroll
    for (int t = 0; t < 4; ++t) {
        *(float2*)(up + i0 * DD + j0 + 8 * t)       = make_float2(acc[t][0], acc[t][1]);
        *(float2*)(up + (i0 + 8) * DD + j0 + 8 * t) = make_float2(acc[t][2], acc[t][3]);
    }
}

// ============================================================================
// kB2: reduce partials -> C^T fp16: g_Cth[h][j][i] = scale * U / Z_i
// ============================================================================
__global__ void kB2() {
    const int idx = blockIdx.x * 256 + threadIdx.x;
    if (idx >= NHEADS * DD * DD) return;
    const int h = idx >> 12;
    const int ij = idx & 4095;
    const int i = ij >> 6, j = ij & 63;
    float u = 0.f;
    #pragma unroll
    for (int c = 0; c < NCB; c++) u += g_Upart[((size_t)(h * NCB + c) << 12) + ij];
    float z = 0.f;
    #pragma unroll
    for (int c = 0; c < NCB; c++) z += g_Zpart[(h * NCB + c) * DD + i];
    const float cval = u * (0.125f / z);
    const __half hv = __float2half(cval);
    g_Cth[h * 4096 + j * 64 + i] = *(const unsigned short*)&hv;
}

// ============================================================================
// kC: per (h, s-tile 64): out[j][s] = rinv[s] * sum_i Ct[j][i] * exp(q[i][s])
// 128 thr / 4 warps; warp owns 16 j-rows x all 64 s. fp16 HMMA single-pass.
// ============================================================================
__global__ __launch_bounds__(128) void kC(const float* __restrict__ Q,
                                          float* __restrict__ O) {
    extern __shared__ __align__(1024) char dsm[];
    char* Asm = dsm;               // Ct fp16 [64 j][64 i], pitch 128B
    char* Bsm = dsm + 8192;        // qe fp16 [64 i][64 s], pitch 128B
    float* rs = (float*)(dsm + 16384);  // [64]

    const int tid = threadIdx.x;
    const int w = tid >> 5, lane = tid & 31;
    const int h = blockIdx.y;
    const int stile = blockIdx.x;
    const float* qh = Q + (size_t)h * DD * SS + stile * SCT;
    float* oh = O + (size_t)h * DD * SS + stile * SCT;

    // Load C^T into swizzled smem (8KB, 4 uint4/thread)
    {
        const unsigned short* src = g_Cth + h * 4096;
        #pragma unroll
        for (int e = 0; e < 4; ++e) {
            const int u = tid + 128 * e;
            const int row = u >> 3, sb = (u & 7) * 16;
            *(uint4*)(Asm + swz(row, sb, 128)) = *(const uint4*)(src + row * 64 + (u & 7) * 8);
        }
    }
    // Convert q tile: 64 i x 64 s -> exp -> fp16. 8 float4/thread.
    #pragma unroll
    for (int e = 0; e < 8; ++e) {
        const int f = tid + 128 * e;
        const int row = f >> 4, c4 = f & 15;
        const float4 q4 = *(const float4*)(qh + (size_t)row * SS + 4 * c4);
        store_h4(Bsm, row, c4, 128,
                 __expf(q4.x), __expf(q4.y), __expf(q4.z), __expf(q4.w));
    }
    __syncthreads();

    // rinv per s column (threads 0..63 own one s each)
    if (tid < 64) {
        float sum = 0.f;
        #pragma unroll 8
        for (int i = 0; i < 64; ++i) {
            const __half hv = *(const __half*)(Bsm + swz(i, 2 * tid, 128));
            sum += __half2float(hv);
        }
        rs[tid] = 1.0f / sum;
    }
    __syncthreads();

    const uint32_t Au = smem_u32(Asm), Bu = smem_u32(Bsm);

    // A fragments (warp's 16 j-rows), reused across all 8 n-tiles.
    uint32_t a[4][4];
    {
        const uint32_t rA = 16 * w + (lane & 15);
        #pragma unroll
        for (int kk = 0; kk < 4; ++kk) {
            const uint32_t cb = 32 * kk + 16 * (lane >> 4);
            ldsm_x4(a[kk][0], a[kk][1], a[kk][2], a[kk][3], Au + swz(rA, cb, 128));
        }
    }

    float acc[8][4];
    #pragma unroll
    for (int t = 0; t < 8; t++)
        #pragma unroll
        for (int e = 0; e < 4; e++) acc[t][e] = 0.f;

    const uint32_t rBl = (lane & 7) + 8 * ((lane >> 3) & 1);  // i row within k16
    #pragma unroll
    for (int nt = 0; nt < 8; ++nt) {
        const uint32_t sb = 2 * (8 * nt);  // byte offset of 8-s group
        #pragma unroll
        for (int kk = 0; kk < 4; ++kk) {
            uint32_t b0, b1;
            ldsm_x2t(b0, b1, Bu + swz(16 * kk + rBl, sb, 128));
            mma_f16(acc[nt], a[kk], b0, b1);
        }
    }

    // Epilogue: scale by rinv and store
    const int j0 = 16 * w + (lane >> 2);
    #pragma unroll
    for (int nt = 0; nt < 8; ++nt) {
        const int sl = 8 * nt + 2 * (lane & 3);
        const float r0 = rs[sl], r1 = rs[sl + 1];
        *(float2*)(oh + (size_t)j0 * SS + sl) =
            make_float2(acc[nt][0] * r0, acc[nt][1] * r1);
        *(float2*)(oh + (size_t)(j0 + 8) * SS + sl) =
            make_float2(acc[nt][2] * r0, acc[nt][3] * r1);
    }
}

extern "C" void kernel_launch(void* const* d_in, const int* in_sizes, int n_in,
                              void* d_out, int out_size) {
    const float* q = (const float*)d_in[0];
    const float* k = (const float*)d_in[1];
    const float* v = (const float*)d_in[2];
    float* out = (float*)d_out;

    dim3 gB(NCB, NHEADS);
    kB<<<gB, 256, KB_SMEM>>>(k, v);
    kB2<<<(NHEADS * DD * DD + 255) / 256, 256>>>();
    dim3 gC(SS / SCT, NHEADS);
    kC<<<gC, 128, KC_SMEM>>>(q, out);
}

// round 14
// speedup vs baseline: 1.3796x; 1.0227x over previous
#include <cuda_runtime.h>
#include <cuda_fp16.h>
#include <cstdint>

// Problem constants: (b=4, n=8, d=64, s=8192) fp32
#define DD 64
#define SS 8192
#define NHEADS 32

// kB config
#define NCB 32
#define CHUNKB (SS / NCB)     // 256
#define NSTAGE (CHUNKB / 64)  // 4
#define KB_SMEM 16384         // A(8KB) + B(8KB) fp16

// kC config
#define SCT 64                // s-tile per block
#define KC_SMEM (8192 + 8192 + 256)

// Scratch
__device__ __half2 g_Upart2[NHEADS * NCB * DD * DD / 2];  // fp16 partials
__device__ float g_Zpart[NHEADS * NCB * DD];
__device__ unsigned short g_Cth[NHEADS * DD * DD];  // C^T fp16 bits, [h][j][i]

// ============================ helpers ============================
__device__ __forceinline__ uint32_t smem_u32(const void* p) {
    uint32_t a;
    asm("{ .reg .u64 t; cvta.to.shared.u64 t, %1; cvt.u32.u64 %0, t; }" : "=r"(a) : "l"(p));
    return a;
}
// XOR swizzle: 16B chunk permute within 128B, keyed by row.
__device__ __forceinline__ uint32_t swz(uint32_t row, uint32_t sbyte, uint32_t pitch) {
    return row * pitch + (sbyte ^ ((row & 7u) << 4));
}
__device__ __forceinline__ void ldsm_x4(uint32_t& r0, uint32_t& r1, uint32_t& r2, uint32_t& r3, uint32_t a) {
    asm volatile("ldmatrix.sync.aligned.m8n8.x4.shared.b16 {%0,%1,%2,%3}, [%4];"
                 : "=r"(r0), "=r"(r1), "=r"(r2), "=r"(r3) : "r"(a));
}
__device__ __forceinline__ void ldsm_x2t(uint32_t& r0, uint32_t& r1, uint32_t a) {
    asm volatile("ldmatrix.sync.aligned.m8n8.x2.trans.shared.b16 {%0,%1}, [%2];"
                 : "=r"(r0), "=r"(r1) : "r"(a));
}
__device__ __forceinline__ void mma_f16(float* d, const uint32_t* a, uint32_t b0, uint32_t b1) {
    asm volatile("mma.sync.aligned.m16n8k16.row.col.f32.f16.f16.f32 "
                 "{%0,%1,%2,%3}, {%4,%5,%6,%7}, {%8,%9}, {%0,%1,%2,%3};"
                 : "+f"(d[0]), "+f"(d[1]), "+f"(d[2]), "+f"(d[3])
                 : "r"(a[0]), "r"(a[1]), "r"(a[2]), "r"(a[3]), "r"(b0), "r"(b1));
}
__device__ __forceinline__ uint32_t cvt2h(float hi, float lo) {  // {high:hi, low:lo}
    uint32_t r;
    asm("cvt.rn.f16x2.f32 %0, %1, %2;" : "=r"(r) : "f"(hi), "f"(lo));
    return r;
}
// Store 4 fp32 as fp16x4 (8B) at swizzled [row][col 4*c4].
__device__ __forceinline__ void store_h4(char* base, int row, int c4, uint32_t pitch,
                                         float a0, float a1, float a2, float a3) {
    *(uint2*)(base + swz(row, 8 * c4, pitch)) = make_uint2(cvt2h(a1, a0), cvt2h(a3, a2));
}

// ============================================================================
// kB: per (h, c): U_part[64i][64j] = sum_s exp(k[i,s]) v[j,s]; Z_part[i].
// fp16 HMMA + register-prefetch software pipeline: stage s+1's LDGs are in
// flight during stage s's MMA phase, keeping DRAM busy across phases.
// 256 thr / 8 warps; warp tile 16i x 32j.
// ============================================================================
__global__ __launch_bounds__(256, 3) void kB(const float* __restrict__ K,
                                             const float* __restrict__ V) {
    extern __shared__ __align__(1024) char dsm[];
    const int tid = threadIdx.x;
    const int w = tid >> 5, lane = tid & 31;
    const int h = blockIdx.y, c = blockIdx.x;
    const float* kh = K + (size_t)h * DD * SS + c * CHUNKB;
    const float* vh = V + (size_t)h * DD * SS + c * CHUNKB;

    const int mt = w & 3;    // i-tile (16 rows)
    const int nh = w >> 2;   // j-half (32 cols)

    float acc[4][4];
    #pragma unroll
    for (int t = 0; t < 4; t++)
        #pragma unroll
        for (int e = 0; e < 4; e++) acc[t][e] = 0.f;
    float zacc[4] = {0.f, 0.f, 0.f, 0.f};

    char* As = dsm;          // expK fp16 [64][64], pitch 128B
    char* Bs = dsm + 8192;   // V    fp16 [64][64], pitch 128B
    const uint32_t Au = smem_u32(As), Bu = smem_u32(Bs);
    const uint32_t rA = 16 * mt + (lane & 15);
    const uint32_t rB = 32 * nh + (lane & 15);

    const int r0 = tid >> 4, c4 = tid & 15;  // loader coords
    const float* kp = kh + (size_t)r0 * SS + 4 * c4;
    const float* vp = vh + (size_t)r0 * SS + 4 * c4;

    // Prologue: load stage 0 into registers.
    float4 pk[4], pv[4];
    #pragma unroll
    for (int e = 0; e < 4; ++e) {
        pk[e] = *(const float4*)(kp + (size_t)(16 * e) * SS);
        pv[e] = *(const float4*)(vp + (size_t)(16 * e) * SS);
    }

    #pragma unroll
    for (int stage = 0; stage < NSTAGE; ++stage) {
        if (stage > 0) __syncthreads();  // smem free (prior MMA readers done)
        // Convert current registers -> fp16 smem (consumes pk/pv).
        #pragma unroll
        for (int e = 0; e < 4; ++e) {
            const int row = r0 + 16 * e;
            const float e0 = __expf(pk[e].x), e1 = __expf(pk[e].y),
                        e2 = __expf(pk[e].z), e3 = __expf(pk[e].w);
            zacc[e] += (e0 + e1) + (e2 + e3);
            store_h4(As, row, c4, 128, e0, e1, e2, e3);
            store_h4(Bs, row, c4, 128, pv[e].x, pv[e].y, pv[e].z, pv[e].w);
        }
        // Prefetch next stage (LDGs overlap the MMA phase below).
        if (stage + 1 < NSTAGE) {
            const int sn = (stage + 1) * 64;
            #pragma unroll
            for (int e = 0; e < 4; ++e) {
                pk[e] = *(const float4*)(kp + (size_t)(16 * e) * SS + sn);
                pv[e] = *(const float4*)(vp + (size_t)(16 * e) * SS + sn);
            }
        }
        __syncthreads();
        // MMA phase on current smem tiles.
        #pragma unroll
        for (int kk = 0; kk < 4; ++kk) {
            const uint32_t cb = 32 * kk + 16 * (lane >> 4);
            uint32_t a[4];
            ldsm_x4(a[0], a[1], a[2], a[3], Au + swz(rA, cb, 128));
            uint32_t b0[4], b1[4];
            ldsm_x4(b0[0], b0[1], b0[2], b0[3], Bu + swz(rB, cb, 128));
            ldsm_x4(b1[0], b1[1], b1[2], b1[3], Bu + swz(rB + 16, cb, 128));
            mma_f16(acc[0], a, b0[0], b0[2]);
            mma_f16(acc[1], a, b0[1], b0[3]);
            mma_f16(acc[2], a, b1[0], b1[2]);
            mma_f16(acc[3], a, b1[1], b1[3]);
        }
    }

    // Z partials: 16 threads share each loader row-group.
    {
        float* zp = g_Zpart + (h * NCB + c) * DD;
        #pragma unroll
        for (int e = 0; e < 4; ++e) {
            float z = zacc[e];
            z += __shfl_down_sync(0xffffffffu, z, 8, 16);
            z += __shfl_down_sync(0xffffffffu, z, 4, 16);
            z += __shfl_down_sync(0xffffffffu, z, 2, 16);
            z += __shfl_down_sync(0xffffffffu, z, 1, 16);
            if ((tid & 15) == 0) zp[(tid >> 4) + 16 * e] = z;
        }
    }

    // acc -> g_Upart (fp16 pairs)
    __half2* up = g_Upart2 + ((size_t)(h * NCB + c) * DD * DD >> 1);
    const int i0 = 16 * mt + (lane >> 2);
    const int j0 = 32 * nh + 2 * (lane & 3);
    #pragma unroll
    for (int t = 0; t < 4; ++t) {
        up[(i0 * DD + j0 + 8 * t) >> 1]       = __floats2half2_rn(acc[t][0], acc[t][1]);
        up[((i0 + 8) * DD + j0 + 8 * t) >> 1] = __floats2half2_rn(acc[t][2], acc[t][3]);
    }
}

// ============================================================================
// kB2: reduce partials -> C^T fp16: g_Cth[h][j][i] = scale * U / Z_i
// ============================================================================
__global__ void kB2() {
    const int idx = blockIdx.x * 256 + threadIdx.x;
    if (idx >= NHEADS * DD * DD) return;
    const int h = idx >> 12;
    const int ij = idx & 4095;
    const int i = ij >> 6, j = ij & 63;
    const __half* U = (const __half*)g_Upart2;
    float u = 0.f;
    #pragma unroll
    for (int c = 0; c < NCB; c++) u += __half2float(U[((size_t)(h * NCB + c) << 12) + ij]);
    float z = 0.f;
    #pragma unroll
    for (int c = 0; c < NCB; c++) z += g_Zpart[(h * NCB + c) * DD + i];
    const float cval = u * (0.125f / z);
    const __half hv = __float2half(cval);
    g_Cth[h * 4096 + j * 64 + i] = *(const unsigned short*)&hv;
}

// ============================================================================
// kC: per (h, s-tile 64): out[j][s] = rinv[s] * sum_i Ct[j][i] * exp(q[i][s])
// 128 thr / 4 warps; warp owns 16 j-rows x all 64 s. fp16 HMMA single-pass.
// ============================================================================
__global__ __launch_bounds__(128) void kC(const float* __restrict__ Q,
                                          float* __restrict__ O) {
    extern __shared__ __align__(1024) char dsm[];
    char* Asm = dsm;               // Ct fp16 [64 j][64 i], pitch 128B
    char* Bsm = dsm + 8192;        // qe fp16 [64 i][64 s], pitch 128B
    float* rs = (float*)(dsm + 16384);  // [64]

    const int tid = threadIdx.x;
    const int w = tid >> 5, lane = tid & 31;
    const int h = blockIdx.y;
    const int stile = blockIdx.x;
    const float* qh = Q + (size_t)h * DD * SS + stile * SCT;
    float* oh = O + (size_t)h * DD * SS + stile * SCT;

    // Load C^T into swizzled smem (8KB, 4 uint4/thread)
    {
        const unsigned short* src = g_Cth + h * 4096;
        #pragma unroll
        for (int e = 0; e < 4; ++e) {
            const int u = tid + 128 * e;
            const int row = u >> 3, sb = (u & 7) * 16;
            *(uint4*)(Asm + swz(row, sb, 128)) = *(const uint4*)(src + row * 64 + (u & 7) * 8);
        }
    }
    // Convert q tile: 64 i x 64 s -> exp -> fp16. 8 float4/thread.
    #pragma unroll
    for (int e = 0; e < 8; ++e) {
        const int f = tid + 128 * e;
        const int row = f >> 4, c4 = f & 15;
        const float4 q4 = *(const float4*)(qh + (size_t)row * SS + 4 * c4);
        store_h4(Bsm, row, c4, 128,
                 __expf(q4.x), __expf(q4.y), __expf(q4.z), __expf(q4.w));
    }
    __syncthreads();

    // rinv per s column (threads 0..63 own one s each)
    if (tid < 64) {
        float sum = 0.f;
        #pragma unroll 8
        for (int i = 0; i < 64; ++i) {
            const __half hv = *(const __half*)(Bsm + swz(i, 2 * tid, 128));
            sum += __half2float(hv);
        }
        rs[tid] = 1.0f / sum;
    }
    __syncthreads();

    const uint32_t Au = smem_u32(Asm), Bu = smem_u32(Bsm);

    // A fragments (warp's 16 j-rows), reused across all 8 n-tiles.
    uint32_t a[4][4];
    {
        const uint32_t rA = 16 * w + (lane & 15);
        #pragma unroll
        for (int kk = 0; kk < 4; ++kk) {
            const uint32_t cb = 32 * kk + 16 * (lane >> 4);
            ldsm_x4(a[kk][0], a[kk][1], a[kk][2], a[kk][3], Au + swz(rA, cb, 128));
        }
    }

    float acc[8][4];
    #pragma unroll
    for (int t = 0; t < 8; t++)
        #pragma unroll
        for (int e = 0; e < 4; e++) acc[t][e] = 0.f;

    const uint32_t rBl = (lane & 7) + 8 * ((lane >> 3) & 1);  // i row within k16
    #pragma unroll
    for (int nt = 0; nt < 8; ++nt) {
        const uint32_t sb = 2 * (8 * nt);  // byte offset of 8-s group
        #pragma unroll
        for (int kk = 0; kk < 4; ++kk) {
            uint32_t b0, b1;
            ldsm_x2t(b0, b1, Bu + swz(16 * kk + rBl, sb, 128));
            mma_f16(acc[nt], a[kk], b0, b1);
        }
    }

    // Epilogue: scale by rinv and store
    const int j0 = 16 * w + (lane >> 2);
    #pragma unroll
    for (int nt = 0; nt < 8; ++nt) {
        const int sl = 8 * nt + 2 * (lane & 3);
        const float r0 = rs[sl], r1 = rs[sl + 1];
        *(float2*)(oh + (size_t)j0 * SS + sl) =
            make_float2(acc[nt][0] * r0, acc[nt][1] * r1);
        *(float2*)(oh + (size_t)(j0 + 8) * SS + sl) =
            make_float2(acc[nt][2] * r0, acc[nt][3] * r1);
    }
}

extern "C" void kernel_launch(void* const* d_in, const int* in_sizes, int n_in,
                              void* d_out, int out_size) {
    const float* q = (const float*)d_in[0];
    const float* k = (const float*)d_in[1];
    const float* v = (const float*)d_in[2];
    float* out = (float*)d_out;

    dim3 gB(NCB, NHEADS);
    kB<<<gB, 256, KB_SMEM>>>(k, v);
    kB2<<<(NHEADS * DD * DD + 255) / 256, 256>>>();
    dim3 gC(SS / SCT, NHEADS);
    kC<<<gC, 128, KC_SMEM>>>(q, out);
}

// round 16
// speedup vs baseline: 1.4925x; 1.0819x over previous
#include <cuda_runtime.h>
#include <cuda_fp16.h>
#include <cstdint>

// Problem constants: (b=4, n=8, d=64, s=8192) fp32
#define DD 64
#define SS 8192
#define NHEADS 32

// kB config
#define NCB 32
#define CHUNKB (SS / NCB)     // 256
#define NSTAGE (CHUNKB / 64)  // 4
#define KB_SMEM 49152         // stgK 16K + stgV 16K + A 8K + B 8K

// kC config
#define SCT 128               // s-tile per block (2 x 64 subtiles)
#define KC_SMEM (8192 + 8192 + 16384 + 256)

// Scratch
__device__ __half2 g_Upart2[NHEADS * NCB * DD * DD / 2];  // fp16 partials
__device__ float g_Zpart[NHEADS * NCB * DD];
__device__ unsigned short g_Cth[NHEADS * DD * DD];  // C^T fp16 bits, [h][j][i]

// ============================ helpers ============================
__device__ __forceinline__ uint32_t smem_u32(const void* p) {
    uint32_t a;
    asm("{ .reg .u64 t; cvta.to.shared.u64 t, %1; cvt.u32.u64 %0, t; }" : "=r"(a) : "l"(p));
    return a;
}
#define CP_ASYNC16(dst, src) \
    asm volatile("cp.async.cg.shared.global [%0], [%1], 16;" :: "r"(dst), "l"(src))
#define CP_COMMIT() asm volatile("cp.async.commit_group;" ::: "memory")
#define CP_WAIT0()  asm volatile("cp.async.wait_group 0;" ::: "memory")

// XOR swizzle: 16B chunk permute within 128B, keyed by row.
__device__ __forceinline__ uint32_t swz(uint32_t row, uint32_t sbyte, uint32_t pitch) {
    return row * pitch + (sbyte ^ ((row & 7u) << 4));
}
__device__ __forceinline__ void ldsm_x4(uint32_t& r0, uint32_t& r1, uint32_t& r2, uint32_t& r3, uint32_t a) {
    asm volatile("ldmatrix.sync.aligned.m8n8.x4.shared.b16 {%0,%1,%2,%3}, [%4];"
                 : "=r"(r0), "=r"(r1), "=r"(r2), "=r"(r3) : "r"(a));
}
__device__ __forceinline__ void ldsm_x2t(uint32_t& r0, uint32_t& r1, uint32_t a) {
    asm volatile("ldmatrix.sync.aligned.m8n8.x2.trans.shared.b16 {%0,%1}, [%2];"
                 : "=r"(r0), "=r"(r1) : "r"(a));
}
__device__ __forceinline__ void mma_f16(float* d, const uint32_t* a, uint32_t b0, uint32_t b1) {
    asm volatile("mma.sync.aligned.m16n8k16.row.col.f32.f16.f16.f32 "
                 "{%0,%1,%2,%3}, {%4,%5,%6,%7}, {%8,%9}, {%0,%1,%2,%3};"
                 : "+f"(d[0]), "+f"(d[1]), "+f"(d[2]), "+f"(d[3])
                 : "r"(a[0]), "r"(a[1]), "r"(a[2]), "r"(a[3]), "r"(b0), "r"(b1));
}
__device__ __forceinline__ uint32_t cvt2h(float hi, float lo) {  // {high:hi, low:lo}
    uint32_t r;
    asm("cvt.rn.f16x2.f32 %0, %1, %2;" : "=r"(r) : "f"(hi), "f"(lo));
    return r;
}
// Store 4 fp32 as fp16x4 (8B) at swizzled [row][col 4*c4].
__device__ __forceinline__ void store_h4(char* base, int row, int c4, uint32_t pitch,
                                         float a0, float a1, float a2, float a3) {
    *(uint2*)(base + swz(row, 8 * c4, pitch)) = make_uint2(cvt2h(a1, a0), cvt2h(a3, a2));
}

// ============================================================================
// kB: per (h, c): U_part[64i][64j] = sum_s exp(k[i,s]) v[j,s]; Z_part[i].
// cp.async staging pipeline: stage s+1 raw fp32 streams into smem while
// stage s runs MMA. fp16 HMMA. 256 thr / 8 warps; warp tile 16i x 32j.
// ============================================================================
__global__ __launch_bounds__(256) void kB(const float* __restrict__ K,
                                          const float* __restrict__ V) {
    extern __shared__ __align__(1024) char dsm[];
    char* stgK = dsm;            // fp32 [64][256B]
    char* stgV = dsm + 16384;    // fp32 [64][256B]
    char* As   = dsm + 32768;    // fp16 expK [64][128B] swizzled
    char* Bs   = dsm + 40960;    // fp16 V    [64][128B] swizzled

    const int tid = threadIdx.x;
    const int w = tid >> 5, lane = tid & 31;
    const int h = blockIdx.y, c = blockIdx.x;
    const float* kh = K + (size_t)h * DD * SS + c * CHUNKB;
    const float* vh = V + (size_t)h * DD * SS + c * CHUNKB;

    const int mt = w & 3;    // i-tile (16 rows)
    const int nh = w >> 2;   // j-half (32 cols)

    float acc[4][4];
    #pragma unroll
    for (int t = 0; t < 4; t++)
        #pragma unroll
        for (int e = 0; e < 4; e++) acc[t][e] = 0.f;
    float zacc[4] = {0.f, 0.f, 0.f, 0.f};

    const uint32_t Au = smem_u32(As), Bu = smem_u32(Bs);
    const uint32_t stgKu = smem_u32(stgK), stgVu = smem_u32(stgV);
    const uint32_t rA = 16 * mt + (lane & 15);
    const uint32_t rB = 32 * nh + (lane & 15);
    const int r0 = tid >> 4, c4 = tid & 15;  // convert coords

    // cp.async one 64-s stage of K and V into staging (4 16B chunks each/thread).
    auto issue_stage = [&](int stage) {
        const int s0 = stage * 64;
        #pragma unroll
        for (int e = 0; e < 4; ++e) {
            const int u = tid + 256 * e;
            const int row = u >> 4, cc = u & 15;
            CP_ASYNC16(stgKu + row * 256 + cc * 16, kh + (size_t)row * SS + s0 + cc * 4);
            CP_ASYNC16(stgVu + row * 256 + cc * 16, vh + (size_t)row * SS + s0 + cc * 4);
        }
        CP_COMMIT();
    };

    issue_stage(0);

    #pragma unroll
    for (int stage = 0; stage < NSTAGE; ++stage) {
        CP_WAIT0();
        __syncthreads();  // staging ready; prior MMA done with tiles
        // Convert staging fp32 -> fp16 tiles (+ exp, + Z accum).
        #pragma unroll
        for (int e = 0; e < 4; ++e) {
            const int row = r0 + 16 * e;
            const float4 k4 = *(const float4*)(stgK + row * 256 + c4 * 16);
            const float e0 = __expf(k4.x), e1 = __expf(k4.y),
                        e2 = __expf(k4.z), e3 = __expf(k4.w);
            zacc[e] += (e0 + e1) + (e2 + e3);
            store_h4(As, row, c4, 128, e0, e1, e2, e3);
            const float4 v4 = *(const float4*)(stgV + row * 256 + c4 * 16);
            store_h4(Bs, row, c4, 128, v4.x, v4.y, v4.z, v4.w);
        }
        __syncthreads();  // staging consumed; tiles ready
        if (stage + 1 < NSTAGE) issue_stage(stage + 1);  // overlaps MMA below
        // MMA phase.
        #pragma unroll
        for (int kk = 0; kk < 4; ++kk) {
            const uint32_t cb = 32 * kk + 16 * (lane >> 4);
            uint32_t a[4];
            ldsm_x4(a[0], a[1], a[2], a[3], Au + swz(rA, cb, 128));
            uint32_t b0[4], b1[4];
            ldsm_x4(b0[0], b0[1], b0[2], b0[3], Bu + swz(rB, cb, 128));
            ldsm_x4(b1[0], b1[1], b1[2], b1[3], Bu + swz(rB + 16, cb, 128));
            mma_f16(acc[0], a, b0[0], b0[2]);
            mma_f16(acc[1], a, b0[1], b0[3]);
            mma_f16(acc[2], a, b1[0], b1[2]);
            mma_f16(acc[3], a, b1[1], b1[3]);
        }
    }

    // Z partials: 16 threads share each loader row-group.
    {
        float* zp = g_Zpart + (h * NCB + c) * DD;
        #pragma unroll
        for (int e = 0; e < 4; ++e) {
            float z = zacc[e];
            z += __shfl_down_sync(0xffffffffu, z, 8, 16);
            z += __shfl_down_sync(0xffffffffu, z, 4, 16);
            z += __shfl_down_sync(0xffffffffu, z, 2, 16);
            z += __shfl_down_sync(0xffffffffu, z, 1, 16);
            if ((tid & 15) == 0) zp[(tid >> 4) + 16 * e] = z;
        }
    }

    // acc -> g_Upart (fp16 pairs)
    __half2* up = g_Upart2 + ((size_t)(h * NCB + c) * DD * DD >> 1);
    const int i0 = 16 * mt + (lane >> 2);
    const int j0 = 32 * nh + 2 * (lane & 3);
    #pragma unroll
    for (int t = 0; t < 4; ++t) {
        up[(i0 * DD + j0 + 8 * t) >> 1]       = __floats2half2_rn(acc[t][0], acc[t][1]);
        up[((i0 + 8) * DD + j0 + 8 * t) >> 1] = __floats2half2_rn(acc[t][2], acc[t][3]);
    }
}

// ============================================================================
// kB2: reduce partials -> C^T fp16: g_Cth[h][j][i] = scale * U / Z_i
// ============================================================================
__global__ void kB2() {
    const int idx = blockIdx.x * 256 + threadIdx.x;
    if (idx >= NHEADS * DD * DD) return;
    const int h = idx >> 12;
    const int ij = idx & 4095;
    const int i = ij >> 6, j = ij & 63;
    const __half* U = (const __half*)g_Upart2;
    float u = 0.f;
    #pragma unroll
    for (int c = 0; c < NCB; c++) u += __half2float(U[((size_t)(h * NCB + c) << 12) + ij]);
    float z = 0.f;
    #pragma unroll
    for (int c = 0; c < NCB; c++) z += g_Zpart[(h * NCB + c) * DD + i];
    const float cval = u * (0.125f / z);
    const __half hv = __float2half(cval);
    g_Cth[h * 4096 + j * 64 + i] = *(const unsigned short*)&hv;
}

// ============================================================================
// kC: per (h, s-tile 128 = 2x64): out[j][s] = rinv[s]*sum_i Ct[j][i]*exp(q[i][s])
// cp.async pipeline over subtiles; C^T load amortized. 128 thr / 4 warps;
// warp owns 16 j-rows x 64 s. fp16 HMMA.
// ============================================================================
__global__ __launch_bounds__(128) void kC(const float* __restrict__ Q,
                                          float* __restrict__ O) {
    extern __shared__ __align__(1024) char dsm[];
    char* Asm = dsm;                    // Ct fp16 [64 j][128B] swizzled
    char* Bsm = dsm + 8192;             // qe fp16 [64 i][128B] swizzled
    char* stgQ = dsm + 16384;           // q fp32 [64 i][256B]
    float* rs = (float*)(dsm + 32768);  // [64]

    const int tid = threadIdx.x;
    const int w = tid >> 5, lane = tid & 31;
    const int h = blockIdx.y;
    const int stile = blockIdx.x;
    const float* qh = Q + (size_t)h * DD * SS + stile * SCT;
    float* oh = O + (size_t)h * DD * SS + stile * SCT;

    const uint32_t Au = smem_u32(Asm), Bu = smem_u32(Bsm);
    const uint32_t stgQu = smem_u32(stgQ);

    // cp.async q subtile (64 i x 64 s fp32): 8 chunks/thread.
    auto issue_q = [&](int st) {
        const int s0 = st * 64;
        #pragma unroll
        for (int e = 0; e < 8; ++e) {
            const int u = tid + 128 * e;
            const int row = u >> 4, cc = u & 15;
            CP_ASYNC16(stgQu + row * 256 + cc * 16, qh + (size_t)row * SS + s0 + cc * 4);
        }
        CP_COMMIT();
    };

    // cp.async C^T (fp16, 8KB) into swizzled Asm: 4 chunks/thread; + q subtile 0.
    {
        const unsigned short* src = g_Cth + h * 4096;
        #pragma unroll
        for (int e = 0; e < 4; ++e) {
            const int u = tid + 128 * e;
            const int row = u >> 3, cc = u & 7;
            CP_ASYNC16(Au + swz(row, cc * 16, 128), src + row * 64 + cc * 8);
        }
    }
    issue_q(0);

    uint32_t a[4][4];   // A fragments, loaded once after C arrives
    float accum_unused;
    (void)accum_unused;

    #pragma unroll
    for (int st = 0; st < 2; ++st) {
        CP_WAIT0();
        __syncthreads();  // staging (and C on st=0) ready; Bsm/rs free
        if (st == 0) {
            const uint32_t rAr = 16 * w + (lane & 15);
            #pragma unroll
            for (int kk = 0; kk < 4; ++kk) {
                const uint32_t cb = 32 * kk + 16 * (lane >> 4);
                ldsm_x4(a[kk][0], a[kk][1], a[kk][2], a[kk][3], Au + swz(rAr, cb, 128));
            }
        }
        // Convert stgQ fp32 -> exp -> Bsm fp16. 8 float4/thread.
        #pragma unroll
        for (int e = 0; e < 8; ++e) {
            const int f = tid + 128 * e;
            const int row = f >> 4, c4 = f & 15;
            const float4 q4 = *(const float4*)(stgQ + row * 256 + c4 * 16);
            store_h4(Bsm, row, c4, 128,
                     __expf(q4.x), __expf(q4.y), __expf(q4.z), __expf(q4.w));
        }
        __syncthreads();  // stgQ consumed; Bsm ready
        if (st == 0) issue_q(1);  // overlaps rinv + MMA + store

        // rinv per s column (threads 0..63)
        if (tid < 64) {
            float sum = 0.f;
            #pragma unroll 8
            for (int i = 0; i < 64; ++i) {
                const __half hv = *(const __half*)(Bsm + swz(i, 2 * tid, 128));
                sum += __half2float(hv);
            }
            rs[tid] = 1.0f / sum;
        }
        __syncthreads();  // rs ready

        float acc[8][4];
        #pragma unroll
        for (int t = 0; t < 8; t++)
            #pragma unroll
            for (int e = 0; e < 4; e++) acc[t][e] = 0.f;

        const uint32_t rBl = (lane & 7) + 8 * ((lane >> 3) & 1);
        #pragma unroll
        for (int nt = 0; nt < 8; ++nt) {
            const uint32_t sb = 2 * (8 * nt);
            #pragma unroll
            for (int kk = 0; kk < 4; ++kk) {
                uint32_t b0, b1;
                ldsm_x2t(b0, b1, Bu + swz(16 * kk + rBl, sb, 128));
                mma_f16(acc[nt], a[kk], b0, b1);
            }
        }

        // Epilogue: scale by rinv, store subtile st.
        const int j0 = 16 * w + (lane >> 2);
        #pragma unroll
        for (int nt = 0; nt < 8; ++nt) {
            const int sl = 8 * nt + 2 * (lane & 3);
            const float r0v = rs[sl], r1v = rs[sl + 1];
            *(float2*)(oh + (size_t)j0 * SS + st * 64 + sl) =
                make_float2(acc[nt][0] * r0v, acc[nt][1] * r1v);
            *(float2*)(oh + (size_t)(j0 + 8) * SS + st * 64 + sl) =
                make_float2(acc[nt][2] * r0v, acc[nt][3] * r1v);
        }
        __syncthreads();  // Bsm/rs reuse fence for next subtile
    }
}

extern "C" void kernel_launch(void* const* d_in, const int* in_sizes, int n_in,
                              void* d_out, int out_size) {
    const float* q = (const float*)d_in[0];
    const float* k = (const float*)d_in[1];
    const float* v = (const float*)d_in[2];
    float* out = (float*)d_out;

    static int configured = 0;
    cudaFuncSetAttribute(kB, cudaFuncAttributeMaxDynamicSharedMemorySize, KB_SMEM);
    cudaFuncSetAttribute(kC, cudaFuncAttributeMaxDynamicSharedMemorySize, KC_SMEM);
    (void)configured;

    dim3 gB(NCB, NHEADS);
    kB<<<gB, 256, KB_SMEM>>>(k, v);
    kB2<<<(NHEADS * DD * DD + 255) / 256, 256>>>();
    dim3 gC(SS / SCT, NHEADS);
    kC<<<gC, 128, KC_SMEM>>>(q, out);
}